// round 7
// baseline (speedup 1.0000x reference)
#include <cuda_runtime.h>

#define HH   512
#define WW   512
#define HWSZ (HH * WW)
#define CIN  32
#define COUT 24
#define NP   8

typedef unsigned long long u64;

// ---- B300 packed-f32 helpers (PTX f32x2 ops -> FFMA2 in SASS) ----
__device__ __forceinline__ u64 fma2_(u64 a, u64 b, u64 c) {
    u64 d; asm("fma.rn.f32x2 %0, %1, %2, %3;" : "=l"(d) : "l"(a), "l"(b), "l"(c)); return d;
}
__device__ __forceinline__ u64 add2_(u64 a, u64 b) {
    u64 d; asm("add.rn.f32x2 %0, %1, %2;" : "=l"(d) : "l"(a), "l"(b)); return d;
}
__device__ __forceinline__ u64 mul2_(u64 a, u64 b) {
    u64 d; asm("mul.rn.f32x2 %0, %1, %2;" : "=l"(d) : "l"(a), "l"(b)); return d;
}
__device__ __forceinline__ u64 pack2_(float lo, float hi) {
    u64 r; asm("mov.b64 %0, {%1, %2};" : "=l"(r) : "f"(lo), "f"(hi)); return r;
}
__device__ __forceinline__ float2 unpack2_(u64 v) {
    float lo, hi; asm("mov.b64 {%0, %1}, %2;" : "=f"(lo), "=f"(hi) : "l"(v));
    return make_float2(lo, hi);
}

// Branch-free windowed load: own aligned float4 (v[4..7]) + ONE uniform halo
// load (lane<16 -> tile left-halo float4, lane>=16 -> tile right-halo), window
// neighbors via warp shuffle, lane-0/31 fixups as register SELECTS (never
// branches -- R2's failure was branching around loads). 2 LDG / ~6 wavefronts
// per (stream,row) instead of 3 LDG / ~14.
__device__ __forceinline__ void load_win(
    const float* __restrict__ base, int hcol, bool l0, bool l31, u64 vp[6])
{
    ulonglong2 M = __ldg(reinterpret_cast<const ulonglong2*>(base));       // v[4..7]
    ulonglong2 H = __ldg(reinterpret_cast<const ulonglong2*>(base - 0 + (hcol)));
    u64 Lx = __shfl_up_sync(0xffffffffu, M.x, 1);
    u64 Ly = __shfl_up_sync(0xffffffffu, M.y, 1);
    u64 Rx = __shfl_down_sync(0xffffffffu, M.x, 1);
    u64 Ry = __shfl_down_sync(0xffffffffu, M.y, 1);
    vp[0] = l0  ? H.x : Lx;
    vp[1] = l0  ? H.y : Ly;
    vp[2] = M.x;
    vp[3] = M.y;
    vp[4] = l31 ? H.x : Rx;
    vp[5] = l31 ? H.y : Ry;
}

__global__ void __launch_bounds__(128) bilat_kernel(
    const float* __restrict__ inp, const float* __restrict__ par,
    float* __restrict__ out)
{
    const int lane  = threadIdx.x & 31;
    const int ty    = threadIdx.x >> 5;
    const int tileX = blockIdx.x * 128;
    const int x0    = tileX + lane * 4;
    const int y     = blockIdx.y * 4 + ty;
    const int b     = blockIdx.z;

    const float* __restrict__ parb = par + b * (NP * HWSZ);
    const float* __restrict__ inpb = inp + b * (CIN * HWSZ);
    float* __restrict__ outb = out + b * (COUT * HWSZ);

    const bool l0  = (lane == 0);
    const bool l31 = (lane == 31);
    // halo column RELATIVE to x0: lane<16 -> tile left halo, else right halo
    const int hcol = ((lane < 16) ? max(tileX - 4, 0)
                                  : min(tileX + 128, WW - 4)) - x0;

    const int cbase = y * WW + x0;
    const u64 M1 = 0xBF800000BF800000ull;   // (-1.0f, -1.0f)

    // x-direction OOB masks (branch-free, computed once)
    u64 mX[5][2];
#pragma unroll
    for (int dx = 0; dx < 5; ++dx) {
        const int g = x0 + dx * 2 - 4;      // global x of tap for pixel 0
        mX[dx][0] = pack2_(((unsigned)(g + 0) < (unsigned)WW) ? 1.0f : 0.0f,
                           ((unsigned)(g + 1) < (unsigned)WW) ? 1.0f : 0.0f);
        mX[dx][1] = pack2_(((unsigned)(g + 2) < (unsigned)WW) ? 1.0f : 0.0f,
                           ((unsigned)(g + 3) < (unsigned)WW) ? 1.0f : 0.0f);
    }

    u64 acc[COUT][2];
#pragma unroll
    for (int c = 0; c < COUT; ++c) { acc[c][0] = 0ull; acc[c][1] = 0ull; }
    u64 ws0 = 0ull, ws1 = 0ull;

#pragma unroll
    for (int dy = 0; dy < 5; ++dy) {
        const int   ny = y + dy * 2 - 4;
        const float mr = ((unsigned)ny < (unsigned)HH) ? 1.0f : 0.0f;
        const int   ro = min(max(ny, 0), HH - 1) * WW;

        // ---- squared param distances ----
        u64 d2[5][2];
#pragma unroll
        for (int dx = 0; dx < 5; ++dx) { d2[dx][0] = 0ull; d2[dx][1] = 0ull; }

#pragma unroll
        for (int p = 0; p < NP; ++p) {
            const float* pr = parb + p * HWSZ;
            ulonglong2 cc = __ldg(reinterpret_cast<const ulonglong2*>(pr + cbase));
            u64 vp[6];
            load_win(pr + ro + x0, hcol, l0, l31, vp);
#pragma unroll
            for (int dx = 0; dx < 5; ++dx) {
                u64 t0 = fma2_(vp[dx],     M1, cc.x);   // neighbor - center
                u64 t1 = fma2_(vp[dx + 1], M1, cc.y);
                d2[dx][0] = fma2_(t0, t0, d2[dx][0]);
                d2[dx][1] = fma2_(t1, t1, d2[dx][1]);
            }
        }

        // ---- raw weights for this dy (ephemeral) ----
        u64 w[5][2];
        const u64 mrow = pack2_(mr, mr);
#pragma unroll
        for (int dx = 0; dx < 5; ++dx) {
            float2 a = unpack2_(d2[dx][0]);
            float2 c = unpack2_(d2[dx][1]);
            u64 e0 = mul2_(pack2_(__expf(-a.x), __expf(-a.y)), mul2_(mX[dx][0], mrow));
            u64 e1 = mul2_(pack2_(__expf(-c.x), __expf(-c.y)), mul2_(mX[dx][1], mrow));
            w[dx][0] = e0;
            w[dx][1] = e1;
            ws0 = add2_(ws0, e0);
            ws1 = add2_(ws1, e1);
        }

        // ---- 24-channel accumulate ----
#pragma unroll
        for (int ch = 0; ch < COUT; ++ch) {
            u64 vp[6];
            load_win(inpb + ch * HWSZ + ro + x0, hcol, l0, l31, vp);
#pragma unroll
            for (int dx = 0; dx < 5; ++dx) {
                acc[ch][0] = fma2_(w[dx][0], vp[dx],     acc[ch][0]);
                acc[ch][1] = fma2_(w[dx][1], vp[dx + 1], acc[ch][1]);
            }
        }
    }

    // ---- normalize once at the store ----
    float2 s0 = unpack2_(ws0), s1 = unpack2_(ws1);
    const u64 r0 = pack2_(__fdividef(1.0f, s0.x + 1e-8f),
                          __fdividef(1.0f, s0.y + 1e-8f));
    const u64 r1 = pack2_(__fdividef(1.0f, s1.x + 1e-8f),
                          __fdividef(1.0f, s1.y + 1e-8f));

#pragma unroll
    for (int ch = 0; ch < COUT; ++ch) {
        float2 f0 = unpack2_(mul2_(acc[ch][0], r0));
        float2 f1 = unpack2_(mul2_(acc[ch][1], r1));
        *reinterpret_cast<float4*>(outb + ch * HWSZ + cbase) =
            make_float4(f0.x, f0.y, f1.x, f1.y);
    }
}

extern "C" void kernel_launch(void* const* d_in, const int* in_sizes, int n_in,
                              void* d_out, int out_size)
{
    const float* inp = (const float*)d_in[0];   // (4,32,512,512) f32
    const float* par = (const float*)d_in[1];   // (4, 8,512,512) f32
    if (n_in >= 2 && in_sizes[0] < in_sizes[1]) {
        const float* t = inp; inp = par; par = t;
    }
    float* out = (float*)d_out;                 // (4,24,512,512) f32

    dim3 grid(WW / 128, HH / 4, 4);
    dim3 block(128);
    bilat_kernel<<<grid, block>>>(inp, par, out);
}

// round 8
// speedup vs baseline: 1.0142x; 1.0142x over previous
#include <cuda_runtime.h>

#define HH   512
#define WW   512
#define HWSZ (HH * WW)
#define CIN  32
#define COUT 24
#define NP   8
#define CHB  12   // channels per CTA (COUT/2)

typedef unsigned long long u64;

__device__ __forceinline__ u64 fma2_(u64 a, u64 b, u64 c) {
    u64 d; asm("fma.rn.f32x2 %0, %1, %2, %3;" : "=l"(d) : "l"(a), "l"(b), "l"(c)); return d;
}
__device__ __forceinline__ u64 add2_(u64 a, u64 b) {
    u64 d; asm("add.rn.f32x2 %0, %1, %2;" : "=l"(d) : "l"(a), "l"(b)); return d;
}
__device__ __forceinline__ u64 mul2_(u64 a, u64 b) {
    u64 d; asm("mul.rn.f32x2 %0, %1, %2;" : "=l"(d) : "l"(a), "l"(b)); return d;
}
__device__ __forceinline__ u64 pack2_(float lo, float hi) {
    u64 r; asm("mov.b64 %0, {%1, %2};" : "=l"(r) : "f"(lo), "f"(hi)); return r;
}
__device__ __forceinline__ float2 unpack2_(u64 v) {
    float lo, hi; asm("mov.b64 {%0, %1}, %2;" : "=f"(lo), "=f"(hi) : "l"(v));
    return make_float2(lo, hi);
}

// Output-row sharing: each thread produces 2 output rows (yA, yA+2) x 4 px x
// 12 channels. Their dilated tap rows overlap: 6 distinct input rows serve
// 2x5 taps, so channel/param window loads amortize ~1.67x. Channel dim is
// split across 2 CTAs (params read twice -- net crossbar still ~16% lower).
// 3-load window gather (R7 proved SHFL pays the same crossbar), full unroll,
// no min-blocks cap (registers = MLP budget).
__global__ void __launch_bounds__(128) bilat_kernel(
    const float* __restrict__ inp, const float* __restrict__ par,
    float* __restrict__ out)
{
    const int lane = threadIdx.x & 31;
    const int wid  = threadIdx.x >> 5;
    const int x0   = blockIdx.x * 128 + lane * 4;
    const int yA   = blockIdx.y * 8 + (wid >> 1) * 4 + (wid & 1);
    const int yB   = yA + 2;
    const int b    = blockIdx.z >> 1;
    const int h    = blockIdx.z & 1;

    const float* __restrict__ parb = par + b * (NP * HWSZ);
    const float* __restrict__ inpb = inp + b * (CIN * HWSZ) + h * (CHB * HWSZ);
    float* __restrict__ outb = out + b * (COUT * HWSZ) + h * (CHB * HWSZ);

    const int xa = max(x0 - 4, 0);
    const int xb = x0;
    const int xc = min(x0 + 4, WW - 4);

    const int cbA = yA * WW + x0;
    const int cbB = yB * WW + x0;
    const u64 M1 = 0xBF800000BF800000ull;   // (-1.0f, -1.0f)

    // x-direction OOB masks (same for both rows)
    u64 mX[5][2];
#pragma unroll
    for (int dx = 0; dx < 5; ++dx) {
        const int g = x0 + dx * 2 - 4;
        mX[dx][0] = pack2_(((unsigned)(g + 0) < (unsigned)WW) ? 1.0f : 0.0f,
                           ((unsigned)(g + 1) < (unsigned)WW) ? 1.0f : 0.0f);
        mX[dx][1] = pack2_(((unsigned)(g + 2) < (unsigned)WW) ? 1.0f : 0.0f,
                           ((unsigned)(g + 3) < (unsigned)WW) ? 1.0f : 0.0f);
    }

    u64 accA[CHB][2], accB[CHB][2];
#pragma unroll
    for (int c = 0; c < CHB; ++c) {
        accA[c][0] = 0ull; accA[c][1] = 0ull;
        accB[c][0] = 0ull; accB[c][1] = 0ull;
    }
    u64 wsA0 = 0ull, wsA1 = 0ull, wsB0 = 0ull, wsB1 = 0ull;

#pragma unroll
    for (int k = 0; k < 6; ++k) {          // input rows yA-4+2k
        const int   r  = yA - 4 + 2 * k;
        const float mr = ((unsigned)r < (unsigned)HH) ? 1.0f : 0.0f;
        const int   ro = min(max(r, 0), HH - 1) * WW;
        const u64   mrow = pack2_(mr, mr);
        // k<5: row feeds output A (dy=k); k>=1: feeds output B (dy=k-1)

        // ---- squared param distances for both centers ----
        u64 d2A[5][2], d2B[5][2];
#pragma unroll
        for (int dx = 0; dx < 5; ++dx) {
            d2A[dx][0] = 0ull; d2A[dx][1] = 0ull;
            d2B[dx][0] = 0ull; d2B[dx][1] = 0ull;
        }

#pragma unroll
        for (int p = 0; p < NP; ++p) {
            const float* pr = parb + p * HWSZ;
            ulonglong2 l0 = __ldg(reinterpret_cast<const ulonglong2*>(pr + ro + xa));
            ulonglong2 l1 = __ldg(reinterpret_cast<const ulonglong2*>(pr + ro + xb));
            ulonglong2 l2 = __ldg(reinterpret_cast<const ulonglong2*>(pr + ro + xc));
            u64 vp[6] = { l0.x, l0.y, l1.x, l1.y, l2.x, l2.y };
            if (k < 5) {
                ulonglong2 cc = __ldg(reinterpret_cast<const ulonglong2*>(pr + cbA));
#pragma unroll
                for (int dx = 0; dx < 5; ++dx) {
                    u64 t0 = fma2_(vp[dx],     M1, cc.x);
                    u64 t1 = fma2_(vp[dx + 1], M1, cc.y);
                    d2A[dx][0] = fma2_(t0, t0, d2A[dx][0]);
                    d2A[dx][1] = fma2_(t1, t1, d2A[dx][1]);
                }
            }
            if (k >= 1) {
                ulonglong2 cc = __ldg(reinterpret_cast<const ulonglong2*>(pr + cbB));
#pragma unroll
                for (int dx = 0; dx < 5; ++dx) {
                    u64 t0 = fma2_(vp[dx],     M1, cc.x);
                    u64 t1 = fma2_(vp[dx + 1], M1, cc.y);
                    d2B[dx][0] = fma2_(t0, t0, d2B[dx][0]);
                    d2B[dx][1] = fma2_(t1, t1, d2B[dx][1]);
                }
            }
        }

        // ---- weights ----
        u64 wA[5][2], wB[5][2];
#pragma unroll
        for (int dx = 0; dx < 5; ++dx) {
            const u64 mA = mul2_(mX[dx][0], mrow);
            const u64 mB = mul2_(mX[dx][1], mrow);
            if (k < 5) {
                float2 a = unpack2_(d2A[dx][0]);
                float2 c = unpack2_(d2A[dx][1]);
                u64 e0 = mul2_(pack2_(__expf(-a.x), __expf(-a.y)), mA);
                u64 e1 = mul2_(pack2_(__expf(-c.x), __expf(-c.y)), mB);
                wA[dx][0] = e0; wA[dx][1] = e1;
                wsA0 = add2_(wsA0, e0); wsA1 = add2_(wsA1, e1);
            }
            if (k >= 1) {
                float2 a = unpack2_(d2B[dx][0]);
                float2 c = unpack2_(d2B[dx][1]);
                u64 e0 = mul2_(pack2_(__expf(-a.x), __expf(-a.y)), mA);
                u64 e1 = mul2_(pack2_(__expf(-c.x), __expf(-c.y)), mB);
                wB[dx][0] = e0; wB[dx][1] = e1;
                wsB0 = add2_(wsB0, e0); wsB1 = add2_(wsB1, e1);
            }
        }

        // ---- 12-channel accumulate, loads shared by both outputs ----
#pragma unroll
        for (int ch = 0; ch < CHB; ++ch) {
            const float* ir = inpb + ch * HWSZ + ro;
            ulonglong2 l0 = __ldg(reinterpret_cast<const ulonglong2*>(ir + xa));
            ulonglong2 l1 = __ldg(reinterpret_cast<const ulonglong2*>(ir + xb));
            ulonglong2 l2 = __ldg(reinterpret_cast<const ulonglong2*>(ir + xc));
            u64 vp[6] = { l0.x, l0.y, l1.x, l1.y, l2.x, l2.y };
#pragma unroll
            for (int dx = 0; dx < 5; ++dx) {
                if (k < 5) {
                    accA[ch][0] = fma2_(wA[dx][0], vp[dx],     accA[ch][0]);
                    accA[ch][1] = fma2_(wA[dx][1], vp[dx + 1], accA[ch][1]);
                }
                if (k >= 1) {
                    accB[ch][0] = fma2_(wB[dx][0], vp[dx],     accB[ch][0]);
                    accB[ch][1] = fma2_(wB[dx][1], vp[dx + 1], accB[ch][1]);
                }
            }
        }
    }

    // ---- normalize and store both rows ----
    float2 sA0 = unpack2_(wsA0), sA1 = unpack2_(wsA1);
    float2 sB0 = unpack2_(wsB0), sB1 = unpack2_(wsB1);
    const u64 rA0 = pack2_(__fdividef(1.0f, sA0.x + 1e-8f),
                           __fdividef(1.0f, sA0.y + 1e-8f));
    const u64 rA1 = pack2_(__fdividef(1.0f, sA1.x + 1e-8f),
                           __fdividef(1.0f, sA1.y + 1e-8f));
    const u64 rB0 = pack2_(__fdividef(1.0f, sB0.x + 1e-8f),
                           __fdividef(1.0f, sB0.y + 1e-8f));
    const u64 rB1 = pack2_(__fdividef(1.0f, sB1.x + 1e-8f),
                           __fdividef(1.0f, sB1.y + 1e-8f));

#pragma unroll
    for (int ch = 0; ch < CHB; ++ch) {
        float2 f0 = unpack2_(mul2_(accA[ch][0], rA0));
        float2 f1 = unpack2_(mul2_(accA[ch][1], rA1));
        *reinterpret_cast<float4*>(outb + ch * HWSZ + cbA) =
            make_float4(f0.x, f0.y, f1.x, f1.y);
        float2 g0 = unpack2_(mul2_(accB[ch][0], rB0));
        float2 g1 = unpack2_(mul2_(accB[ch][1], rB1));
        *reinterpret_cast<float4*>(outb + ch * HWSZ + cbB) =
            make_float4(g0.x, g0.y, g1.x, g1.y);
    }
}

extern "C" void kernel_launch(void* const* d_in, const int* in_sizes, int n_in,
                              void* d_out, int out_size)
{
    const float* inp = (const float*)d_in[0];   // (4,32,512,512) f32
    const float* par = (const float*)d_in[1];   // (4, 8,512,512) f32
    if (n_in >= 2 && in_sizes[0] < in_sizes[1]) {
        const float* t = inp; inp = par; par = t;
    }
    float* out = (float*)d_out;                 // (4,24,512,512) f32

    dim3 grid(WW / 128, HH / 8, 4 * 2);         // x-tiles, 8-row bands, batch x ch-half
    dim3 block(128);
    bilat_kernel<<<grid, block>>>(inp, par, out);
}

// round 9
// speedup vs baseline: 1.1861x; 1.1695x over previous
#include <cuda_runtime.h>

#define HH   512
#define WW   512
#define HWSZ (HH * WW)
#define CIN  32
#define COUT 24
#define NP   8

typedef unsigned long long u64;

__device__ __forceinline__ u64 fma2_(u64 a, u64 b, u64 c) {
    u64 d; asm("fma.rn.f32x2 %0, %1, %2, %3;" : "=l"(d) : "l"(a), "l"(b), "l"(c)); return d;
}
__device__ __forceinline__ u64 add2_(u64 a, u64 b) {
    u64 d; asm("add.rn.f32x2 %0, %1, %2;" : "=l"(d) : "l"(a), "l"(b)); return d;
}
__device__ __forceinline__ u64 mul2_(u64 a, u64 b) {
    u64 d; asm("mul.rn.f32x2 %0, %1, %2;" : "=l"(d) : "l"(a), "l"(b)); return d;
}
__device__ __forceinline__ u64 pack2_(float lo, float hi) {
    u64 r; asm("mov.b64 %0, {%1, %2};" : "=l"(r) : "f"(lo), "f"(hi)); return r;
}
__device__ __forceinline__ float2 unpack2_(u64 v) {
    float lo, hi; asm("mov.b64 {%0, %1}, %2;" : "=f"(lo), "=f"(hi) : "l"(v));
    return make_float2(lo, hi);
}

#define M1C 0xBF800000BF800000ull   /* (-1.0f, -1.0f) */

// squared param distances for one tap row (hoisted center values in cc)
__device__ __forceinline__ void d2_row(
    const float* __restrict__ parb, int ro, int xa, int xb, int xc,
    const u64* __restrict__ ccx, const u64* __restrict__ ccy, u64 d2[5][2])
{
#pragma unroll
    for (int dx = 0; dx < 5; ++dx) { d2[dx][0] = 0ull; d2[dx][1] = 0ull; }
#pragma unroll
    for (int p = 0; p < NP; ++p) {
        const float* pr = parb + p * HWSZ + ro;
        ulonglong2 l0 = __ldg(reinterpret_cast<const ulonglong2*>(pr + xa));
        ulonglong2 l1 = __ldg(reinterpret_cast<const ulonglong2*>(pr + xb));
        ulonglong2 l2 = __ldg(reinterpret_cast<const ulonglong2*>(pr + xc));
        u64 vp[6] = { l0.x, l0.y, l1.x, l1.y, l2.x, l2.y };
#pragma unroll
        for (int dx = 0; dx < 5; ++dx) {
            u64 t0 = fma2_(vp[dx],     M1C, ccx[p]);
            u64 t1 = fma2_(vp[dx + 1], M1C, ccy[p]);
            d2[dx][0] = fma2_(t0, t0, d2[dx][0]);
            d2[dx][1] = fma2_(t1, t1, d2[dx][1]);
        }
    }
}

// Skewed software pipeline over dy (fully unrolled): at stage dy the weights
// are produced from d2 computed during stage dy-1, the NEXT row's param loads
// + d2 FMAs are issued up front, and the 24-channel FMA block (~500 issue
// cycles) covers their latency. Center params loaded once (not per dy).
// Registers deliberately uncapped: they are the MLP budget.
__global__ void __launch_bounds__(128) bilat_kernel(
    const float* __restrict__ inp, const float* __restrict__ par,
    float* __restrict__ out)
{
    const int lane = threadIdx.x & 31;
    const int ty   = threadIdx.x >> 5;
    const int x0   = blockIdx.x * 128 + lane * 4;
    const int y    = blockIdx.y * 4 + ty;
    const int b    = blockIdx.z;

    const float* __restrict__ parb = par + b * (NP * HWSZ);
    const float* __restrict__ inpb = inp + b * (CIN * HWSZ);
    float* __restrict__ outb = out + b * (COUT * HWSZ);

    const int xa = max(x0 - 4, 0);
    const int xb = x0;
    const int xc = min(x0 + 4, WW - 4);

    const int cbase = y * WW + x0;

    // hoisted center params (read once, reused by all 5 dy stages)
    u64 ccx[NP], ccy[NP];
#pragma unroll
    for (int p = 0; p < NP; ++p) {
        ulonglong2 cc = __ldg(reinterpret_cast<const ulonglong2*>(parb + p * HWSZ + cbase));
        ccx[p] = cc.x; ccy[p] = cc.y;
    }

    // x-direction OOB masks
    u64 mX[5][2];
#pragma unroll
    for (int dx = 0; dx < 5; ++dx) {
        const int g = x0 + dx * 2 - 4;
        mX[dx][0] = pack2_(((unsigned)(g + 0) < (unsigned)WW) ? 1.0f : 0.0f,
                           ((unsigned)(g + 1) < (unsigned)WW) ? 1.0f : 0.0f);
        mX[dx][1] = pack2_(((unsigned)(g + 2) < (unsigned)WW) ? 1.0f : 0.0f,
                           ((unsigned)(g + 3) < (unsigned)WW) ? 1.0f : 0.0f);
    }

    int roA[5];
    float mrA[5];
#pragma unroll
    for (int dy = 0; dy < 5; ++dy) {
        const int ny = y + dy * 2 - 4;
        mrA[dy] = ((unsigned)ny < (unsigned)HH) ? 1.0f : 0.0f;
        roA[dy] = min(max(ny, 0), HH - 1) * WW;
    }

    u64 acc[COUT][2];
#pragma unroll
    for (int c = 0; c < COUT; ++c) { acc[c][0] = 0ull; acc[c][1] = 0ull; }
    u64 ws0 = 0ull, ws1 = 0ull;

    // prologue: d2 for dy=0
    u64 d2c[5][2];
    d2_row(parb, roA[0], xa, xb, xc, ccx, ccy, d2c);

#pragma unroll
    for (int dy = 0; dy < 5; ++dy) {
        // ---- 1. weights for this dy from d2c (computed a stage earlier) ----
        u64 w[5][2];
        const u64 mrow = pack2_(mrA[dy], mrA[dy]);
#pragma unroll
        for (int dx = 0; dx < 5; ++dx) {
            float2 a = unpack2_(d2c[dx][0]);
            float2 c = unpack2_(d2c[dx][1]);
            u64 e0 = mul2_(pack2_(__expf(-a.x), __expf(-a.y)), mul2_(mX[dx][0], mrow));
            u64 e1 = mul2_(pack2_(__expf(-c.x), __expf(-c.y)), mul2_(mX[dx][1], mrow));
            w[dx][0] = e0;
            w[dx][1] = e1;
            ws0 = add2_(ws0, e0);
            ws1 = add2_(ws1, e1);
        }

        // ---- 2. kick off next row's param loads + d2 (latency hidden by 3.) ----
        u64 d2n[5][2];
        if (dy < 4)
            d2_row(parb, roA[dy + 1], xa, xb, xc, ccx, ccy, d2n);

        // ---- 3. 24-channel accumulate for this dy ----
        const int ro = roA[dy];
#pragma unroll
        for (int ch = 0; ch < COUT; ++ch) {
            const float* ir = inpb + ch * HWSZ + ro;
            ulonglong2 l0 = __ldg(reinterpret_cast<const ulonglong2*>(ir + xa));
            ulonglong2 l1 = __ldg(reinterpret_cast<const ulonglong2*>(ir + xb));
            ulonglong2 l2 = __ldg(reinterpret_cast<const ulonglong2*>(ir + xc));
            u64 vp[6] = { l0.x, l0.y, l1.x, l1.y, l2.x, l2.y };
#pragma unroll
            for (int dx = 0; dx < 5; ++dx) {
                acc[ch][0] = fma2_(w[dx][0], vp[dx],     acc[ch][0]);
                acc[ch][1] = fma2_(w[dx][1], vp[dx + 1], acc[ch][1]);
            }
        }

        // ---- 4. rotate pipeline ----
        if (dy < 4) {
#pragma unroll
            for (int dx = 0; dx < 5; ++dx) {
                d2c[dx][0] = d2n[dx][0];
                d2c[dx][1] = d2n[dx][1];
            }
        }
    }

    // ---- normalize once at the store ----
    float2 s0 = unpack2_(ws0), s1 = unpack2_(ws1);
    const u64 r0 = pack2_(__fdividef(1.0f, s0.x + 1e-8f),
                          __fdividef(1.0f, s0.y + 1e-8f));
    const u64 r1 = pack2_(__fdividef(1.0f, s1.x + 1e-8f),
                          __fdividef(1.0f, s1.y + 1e-8f));

#pragma unroll
    for (int ch = 0; ch < COUT; ++ch) {
        float2 f0 = unpack2_(mul2_(acc[ch][0], r0));
        float2 f1 = unpack2_(mul2_(acc[ch][1], r1));
        *reinterpret_cast<float4*>(outb + ch * HWSZ + cbase) =
            make_float4(f0.x, f0.y, f1.x, f1.y);
    }
}

extern "C" void kernel_launch(void* const* d_in, const int* in_sizes, int n_in,
                              void* d_out, int out_size)
{
    const float* inp = (const float*)d_in[0];   // (4,32,512,512) f32
    const float* par = (const float*)d_in[1];   // (4, 8,512,512) f32
    if (n_in >= 2 && in_sizes[0] < in_sizes[1]) {
        const float* t = inp; inp = par; par = t;
    }
    float* out = (float*)d_out;                 // (4,24,512,512) f32

    dim3 grid(WW / 128, HH / 4, 4);
    dim3 block(128);
    bilat_kernel<<<grid, block>>>(inp, par, out);
}